// round 1
// baseline (speedup 1.0000x reference)
#include <cuda_runtime.h>

#define BATCH 32
#define NP    576          // patches per image (24x24)
#define NTXT  77
#define NTOK  654          // 1 + 576 + 77
#define EMB   768
#define HD    384          // head dim (2 heads)
#define INV_SQRT_E 0.03608439182435161f   // 1/sqrt(768)

// ---------------- scratch (static device allocations; no runtime alloc) ----
__device__ float g_t[(size_t)BATCH * NTOK * EMB];   // token stream
__device__ float g_h[(size_t)BATCH * NTOK * EMB];   // LN1 out, later proj out
__device__ float g_q[(size_t)BATCH * NTOK * EMB];
__device__ float g_k[(size_t)BATCH * NTOK * EMB];
__device__ float g_v[(size_t)BATCH * NTOK * EMB];
__device__ float g_o[(size_t)BATCH * NTOK * EMB];   // first: patches buffer; later: attn out
__device__ float g_s[(size_t)BATCH * 2 * NTOK * NTOK];  // attention scores
__device__ float g_m[BATCH * EMB];                  // pooled

// ---------------- reductions ----------------
__device__ __forceinline__ float warpSum(float v) {
#pragma unroll
    for (int o = 16; o; o >>= 1) v += __shfl_xor_sync(0xffffffffu, v, o);
    return v;
}
__device__ __forceinline__ float warpMax(float v) {
#pragma unroll
    for (int o = 16; o; o >>= 1) v = fmaxf(v, __shfl_xor_sync(0xffffffffu, v, o));
    return v;
}

// ---------------- patch gather: x[B,3,384,384] -> patches[B*576, 768] -------
// patches[(b*576+j)][k], k = p1*48 + p2*3 + c ; j = (hh/16)*24 + ww/16
__global__ void patch_extract(const float* __restrict__ x, float* __restrict__ p) {
    long idx = (long)blockIdx.x * blockDim.x + threadIdx.x;
    const long total = (long)BATCH * 3 * 384 * 384;
    if (idx >= total) return;
    int ww = (int)(idx % 384);
    long t1 = idx / 384;
    int hh = (int)(t1 % 384);
    long t2 = t1 / 384;
    int c = (int)(t2 % 3);
    int b = (int)(t2 / 3);
    int j = (hh >> 4) * 24 + (ww >> 4);
    int k = (hh & 15) * 48 + (ww & 15) * 3 + c;
    p[((long)(b * NP + j)) * EMB + k] = x[idx];
}

// ---------------- fill cls (row 0) and text rows (577..653) ----------------
__global__ void fill_cls_text(const float* __restrict__ cls, const float* __restrict__ txt) {
    long idx = (long)blockIdx.x * blockDim.x + threadIdx.x;
    const long total = (long)BATCH * (1 + NTXT) * EMB;
    if (idx >= total) return;
    int e = (int)(idx % EMB);
    long r = idx / EMB;
    int tok = (int)(r % (1 + NTXT));
    int b = (int)(r / (1 + NTXT));
    if (tok == 0)
        g_t[((long)b * NTOK) * EMB + e] = cls[e];
    else
        g_t[((long)b * NTOK + NP + tok) * EMB + e] = txt[((long)b * NTXT + (tok - 1)) * EMB + e];
}

// ---------------- generic tiled GEMM: C = A[MxK] * W[KxN] + bias -----------
// 64x64 tile, TK=16, 256 threads, 4x4 per thread.
// patch_remap: when nonzero, output row r maps to t-row r + (r/576)*78 + 1.
__global__ void gemm64(const float* __restrict__ A, int lda,
                       const float* __restrict__ Bm, int ldb,
                       const float* __restrict__ bias,
                       float* __restrict__ C, int ldc,
                       int M, int N, int K, int patch_remap) {
    __shared__ float As[16][64];
    __shared__ float Bs[16][64];
    int tid = threadIdx.x;
    int tx = tid & 15, ty = tid >> 4;
    int row0 = blockIdx.y * 64, col0 = blockIdx.x * 64;
    float acc[4][4] = {};
    int ar = tid >> 2, ak = (tid & 3) * 4;   // A loader: 64 rows x 4k each
    int bk = tid >> 4, bc = (tid & 15) * 4;  // B loader: 16 k-rows x 4cols each

    for (int k0 = 0; k0 < K; k0 += 16) {
#pragma unroll
        for (int i = 0; i < 4; i++) {
            int r = row0 + ar, kk = k0 + ak + i;
            As[ak + i][ar] = (r < M && kk < K) ? A[(long)r * lda + kk] : 0.f;
        }
#pragma unroll
        for (int i = 0; i < 4; i++) {
            int kk = k0 + bk, c = col0 + bc + i;
            Bs[bk][bc + i] = (kk < K && c < N) ? Bm[(long)kk * ldb + c] : 0.f;
        }
        __syncthreads();
#pragma unroll
        for (int k = 0; k < 16; k++) {
            float a[4], bb[4];
#pragma unroll
            for (int i = 0; i < 4; i++) a[i] = As[k][ty * 4 + i];
#pragma unroll
            for (int j = 0; j < 4; j++) bb[j] = Bs[k][tx * 4 + j];
#pragma unroll
            for (int i = 0; i < 4; i++)
#pragma unroll
                for (int j = 0; j < 4; j++) acc[i][j] += a[i] * bb[j];
        }
        __syncthreads();
    }
#pragma unroll
    for (int i = 0; i < 4; i++) {
        int r = row0 + ty * 4 + i;
        if (r >= M) continue;
        long orow = patch_remap ? ((long)r + (long)(r / NP) * 78 + 1) : (long)r;
#pragma unroll
        for (int j = 0; j < 4; j++) {
            int c = col0 + tx * 4 + j;
            if (c >= N) continue;
            C[orow * ldc + c] = acc[i][j] + (bias ? bias[c] : 0.f);
        }
    }
}

// ---------------- scores = q @ k^T per (b,h) --------------------------------
__global__ void gemm_scores_kernel() {
    const int z = blockIdx.z, b = z >> 1, hh = z & 1;
    const float* A  = g_q + (long)b * NTOK * EMB + hh * HD;
    const float* Bk = g_k + (long)b * NTOK * EMB + hh * HD;
    float* C = g_s + (long)z * NTOK * NTOK;
    __shared__ float As[16][64];
    __shared__ float Bs[16][64];
    int tid = threadIdx.x;
    int tx = tid & 15, ty = tid >> 4;
    int row0 = blockIdx.y * 64, col0 = blockIdx.x * 64;
    float acc[4][4] = {};
    int ar = tid >> 2, ak = (tid & 3) * 4;

    for (int k0 = 0; k0 < HD; k0 += 16) {   // HD % 16 == 0
#pragma unroll
        for (int i = 0; i < 4; i++) {
            int kk = k0 + ak + i;
            int r = row0 + ar;
            As[ak + i][ar] = (r < NTOK) ? A[(long)r * EMB + kk] : 0.f;
            int c = col0 + ar;
            Bs[ak + i][ar] = (c < NTOK) ? Bk[(long)c * EMB + kk] : 0.f;
        }
        __syncthreads();
#pragma unroll
        for (int k = 0; k < 16; k++) {
            float a[4], bb[4];
#pragma unroll
            for (int i = 0; i < 4; i++) a[i] = As[k][ty * 4 + i];
#pragma unroll
            for (int j = 0; j < 4; j++) bb[j] = Bs[k][tx * 4 + j];
#pragma unroll
            for (int i = 0; i < 4; i++)
#pragma unroll
                for (int j = 0; j < 4; j++) acc[i][j] += a[i] * bb[j];
        }
        __syncthreads();
    }
#pragma unroll
    for (int i = 0; i < 4; i++) {
        int r = row0 + ty * 4 + i;
        if (r >= NTOK) continue;
#pragma unroll
        for (int j = 0; j < 4; j++) {
            int c = col0 + tx * 4 + j;
            if (c >= NTOK) continue;
            C[(long)r * NTOK + c] = acc[i][j];
        }
    }
}

// ---------------- softmax(row) / sqrt(768), in place ------------------------
__global__ void softmax_kernel() {
    long row = blockIdx.x;
    float* r = g_s + row * (long)NTOK;
    int tid = threadIdx.x;
    __shared__ float sh[8];
    __shared__ float shb;

    float mx = -1e30f;
    for (int i = tid; i < NTOK; i += 256) mx = fmaxf(mx, r[i]);
    mx = warpMax(mx);
    if ((tid & 31) == 0) sh[tid >> 5] = mx;
    __syncthreads();
    if (tid == 0) {
        float m = sh[0];
#pragma unroll
        for (int i = 1; i < 8; i++) m = fmaxf(m, sh[i]);
        shb = m;
    }
    __syncthreads();
    mx = shb;

    float sum = 0.f;
    for (int i = tid; i < NTOK; i += 256) {
        float e = __expf(r[i] - mx);
        r[i] = e;
        sum += e;
    }
    sum = warpSum(sum);
    if ((tid & 31) == 0) sh[tid >> 5] = sum;
    __syncthreads();
    if (tid == 0) {
        float s = 0.f;
#pragma unroll
        for (int i = 0; i < 8; i++) s += sh[i];
        shb = s;
    }
    __syncthreads();
    float inv = INV_SQRT_E / shb;
    for (int i = tid; i < NTOK; i += 256) r[i] *= inv;
}

// ---------------- o = attn @ v per (b,h) ------------------------------------
__global__ void gemm_av_kernel() {
    const int z = blockIdx.z, b = z >> 1, hh = z & 1;
    const float* A  = g_s + (long)z * NTOK * NTOK;             // [654,654]
    const float* Bv = g_v + (long)b * NTOK * EMB + hh * HD;    // ldb=EMB, N=HD
    float* C = g_o + (long)b * NTOK * EMB + hh * HD;
    __shared__ float As[16][64];
    __shared__ float Bs[16][64];
    int tid = threadIdx.x;
    int tx = tid & 15, ty = tid >> 4;
    int row0 = blockIdx.y * 64, col0 = blockIdx.x * 64;
    float acc[4][4] = {};
    int ar = tid >> 2, ak = (tid & 3) * 4;
    int bk = tid >> 4, bc = (tid & 15) * 4;

    for (int k0 = 0; k0 < NTOK; k0 += 16) {  // K=654, tail-guarded
#pragma unroll
        for (int i = 0; i < 4; i++) {
            int r = row0 + ar, kk = k0 + ak + i;
            As[ak + i][ar] = (r < NTOK && kk < NTOK) ? A[(long)r * NTOK + kk] : 0.f;
        }
#pragma unroll
        for (int i = 0; i < 4; i++) {
            int kk = k0 + bk, c = col0 + bc + i;
            Bs[bk][bc + i] = (kk < NTOK && c < HD) ? Bv[(long)kk * EMB + c] : 0.f;
        }
        __syncthreads();
#pragma unroll
        for (int k = 0; k < 16; k++) {
            float a[4], bb[4];
#pragma unroll
            for (int i = 0; i < 4; i++) a[i] = As[k][ty * 4 + i];
#pragma unroll
            for (int j = 0; j < 4; j++) bb[j] = Bs[k][tx * 4 + j];
#pragma unroll
            for (int i = 0; i < 4; i++)
#pragma unroll
                for (int j = 0; j < 4; j++) acc[i][j] += a[i] * bb[j];
        }
        __syncthreads();
    }
#pragma unroll
    for (int i = 0; i < 4; i++) {
        int r = row0 + ty * 4 + i;
        if (r >= NTOK) continue;
#pragma unroll
        for (int j = 0; j < 4; j++) {
            int c = col0 + tx * 4 + j;
            if (c >= HD) continue;
            C[(long)r * EMB + c] = acc[i][j];
        }
    }
}

// ---------------- LayerNorm over 768; optionally out += LN(in) --------------
__global__ void ln768_kernel(const float* __restrict__ in,
                             const float* __restrict__ g,
                             const float* __restrict__ be,
                             float* __restrict__ out, int add) {
    long row = blockIdx.x;
    int tid = threadIdx.x;
    const float* r = in + row * EMB;
    float v0 = r[tid], v1 = r[tid + 256], v2 = r[tid + 512];
    float s = v0 + v1 + v2;
    float ss = v0 * v0 + v1 * v1 + v2 * v2;
    s = warpSum(s);
    ss = warpSum(ss);
    __shared__ float sh1[8], sh2[8];
    __shared__ float smean, srstd;
    if ((tid & 31) == 0) { sh1[tid >> 5] = s; sh2[tid >> 5] = ss; }
    __syncthreads();
    if (tid == 0) {
        float a = 0.f, b2 = 0.f;
#pragma unroll
        for (int i = 0; i < 8; i++) { a += sh1[i]; b2 += sh2[i]; }
        float mean = a * (1.f / 768.f);
        smean = mean;
        srstd = rsqrtf(b2 * (1.f / 768.f) - mean * mean + 1e-5f);
    }
    __syncthreads();
    float mean = smean, rstd = srstd;
    float* w = out + row * EMB;
    float vv[3] = {v0, v1, v2};
#pragma unroll
    for (int i = 0; i < 3; i++) {
        int c = tid + i * 256;
        float val = (vv[i] - mean) * rstd * g[c] + be[c];
        if (add) w[c] += val; else w[c] = val;
    }
}

// ---------------- mean pool over tokens -------------------------------------
__global__ void meanpool_kernel() {
    int b = blockIdx.x;
    int e = threadIdx.x;   // 768 threads
    const float* base = g_t + (long)b * NTOK * EMB + e;
    float s = 0.f;
    for (int i = 0; i < NTOK; i++) s += base[(long)i * EMB];
    g_m[b * EMB + e] = s * (1.f / (float)NTOK);
}

// ---------------- launch -----------------------------------------------------
extern "C" void kernel_launch(void* const* d_in, const int* in_sizes, int n_in,
                              void* d_out, int out_size) {
    const float* x    = (const float*)d_in[0];
    const float* txt  = (const float*)d_in[1];
    const float* Wpa  = (const float*)d_in[2];
    const float* bpa  = (const float*)d_in[3];
    const float* cls  = (const float*)d_in[4];
    const float* g1   = (const float*)d_in[5];
    const float* be1  = (const float*)d_in[6];
    const float* Wq   = (const float*)d_in[7];
    const float* bq   = (const float*)d_in[8];
    const float* Wk   = (const float*)d_in[9];
    const float* bk   = (const float*)d_in[10];
    const float* Wv   = (const float*)d_in[11];
    const float* bv   = (const float*)d_in[12];
    const float* Wp   = (const float*)d_in[13];
    const float* bp   = (const float*)d_in[14];
    const float* g2   = (const float*)d_in[15];
    const float* be2  = (const float*)d_in[16];
    const float* g3   = (const float*)d_in[17];
    const float* be3  = (const float*)d_in[18];
    const float* Wf   = (const float*)d_in[19];
    const float* bf   = (const float*)d_in[20];
    float* out = (float*)d_out;

    float *t, *h, *q, *k, *v, *o, *m;
    cudaGetSymbolAddress((void**)&t, g_t);
    cudaGetSymbolAddress((void**)&h, g_h);
    cudaGetSymbolAddress((void**)&q, g_q);
    cudaGetSymbolAddress((void**)&k, g_k);
    cudaGetSymbolAddress((void**)&v, g_v);
    cudaGetSymbolAddress((void**)&o, g_o);
    cudaGetSymbolAddress((void**)&m, g_m);

    const int MQKV = BATCH * NTOK;    // 20928
    const int MPATCH = BATCH * NP;    // 18432

    // 1) patches -> g_o (scratch), cls+text -> g_t
    patch_extract<<<55296, 256>>>(x, o);
    fill_cls_text<<<7488, 256>>>(cls, txt);

    // 2) patch GEMM into g_t (rows remapped past cls)
    gemm64<<<dim3(12, MPATCH / 64), 256>>>(o, EMB, Wpa, EMB, bpa, t, EMB,
                                           MPATCH, EMB, EMB, 1);

    // 3) LN1
    ln768_kernel<<<MQKV, 256>>>(t, g1, be1, h, 0);

    // 4) QKV
    dim3 gq(12, MQKV / 64);
    gemm64<<<gq, 256>>>(h, EMB, Wq, EMB, bq, q, EMB, MQKV, EMB, EMB, 0);
    gemm64<<<gq, 256>>>(h, EMB, Wk, EMB, bk, k, EMB, MQKV, EMB, EMB, 0);
    gemm64<<<gq, 256>>>(h, EMB, Wv, EMB, bv, v, EMB, MQKV, EMB, EMB, 0);

    // 5) attention
    gemm_scores_kernel<<<dim3(11, 11, 64), 256>>>();
    softmax_kernel<<<64 * NTOK, 256>>>();
    gemm_av_kernel<<<dim3(6, 11, 64), 256>>>();

    // 6) proj into g_h, then t += LN2(proj)
    gemm64<<<gq, 256>>>(o, EMB, Wp, EMB, bp, h, EMB, MQKV, EMB, EMB, 0);
    ln768_kernel<<<MQKV, 256>>>(h, g2, be2, t, 1);

    // 7) mean pool, LN3 (in place), final linear -> out
    meanpool_kernel<<<BATCH, 768>>>();
    ln768_kernel<<<BATCH, 256>>>(m, g3, be3, m, 0);
    gemm64<<<dim3(12, 1), 256>>>(m, EMB, Wf, EMB, bf, out, EMB, BATCH, EMB, EMB, 0);
}

// round 3
// speedup vs baseline: 1.8573x; 1.8573x over previous
#include <cuda_runtime.h>
#include <cstdint>

#define BATCH 32
#define NP    576
#define NTXT  77
#define NTOK  654
#define EMB   768
#define HD    384
#define SRS   656          // scores row stride (padded to mult of 16)
#define INV_SQRT_E 0.03608439182435161f

// ---------------- scratch ----------------
__device__ float g_t[(size_t)BATCH * NTOK * EMB];
__device__ float g_h[(size_t)BATCH * NTOK * EMB];
__device__ float g_q[(size_t)BATCH * NTOK * EMB];
__device__ float g_k[(size_t)BATCH * NTOK * EMB];
__device__ float g_v[(size_t)BATCH * NTOK * EMB];
__device__ float g_o[(size_t)BATCH * NTOK * EMB];
__device__ float g_s[(size_t)BATCH * 2 * NTOK * SRS];
__device__ float g_m[BATCH * EMB];

// ---------------- helpers ----------------
__device__ __forceinline__ float warpSum(float v) {
#pragma unroll
    for (int o = 16; o; o >>= 1) v += __shfl_xor_sync(0xffffffffu, v, o);
    return v;
}
__device__ __forceinline__ float warpMax(float v) {
#pragma unroll
    for (int o = 16; o; o >>= 1) v = fmaxf(v, __shfl_xor_sync(0xffffffffu, v, o));
    return v;
}
__device__ __forceinline__ uint32_t f2tf(float f) {
    uint32_t r;
    asm("cvt.rna.tf32.f32 %0, %1;" : "=r"(r) : "f"(f));
    return r;
}
// split into hi (tf32) + lo (tf32 of residual) for 3xTF32 compensation
struct TF2 { uint32_t h, l; };
__device__ __forceinline__ TF2 tfsplit(float f) {
    TF2 r;
    r.h = f2tf(f);
    r.l = f2tf(f - __uint_as_float(r.h));
    return r;
}
__device__ __forceinline__ void mma8(float c[4], uint32_t a0, uint32_t a1,
                                     uint32_t a2, uint32_t a3,
                                     uint32_t b0, uint32_t b1) {
    asm volatile(
        "mma.sync.aligned.m16n8k8.row.col.f32.tf32.tf32.f32 "
        "{%0,%1,%2,%3},{%4,%5,%6,%7},{%8,%9},{%0,%1,%2,%3};"
        : "+f"(c[0]), "+f"(c[1]), "+f"(c[2]), "+f"(c[3])
        : "r"(a0), "r"(a1), "r"(a2), "r"(a3), "r"(b0), "r"(b1));
}
__device__ __forceinline__ void cpa(uint32_t dst, const float* src, bool valid) {
    asm volatile("cp.async.cg.shared.global [%0], [%1], 16, %2;"
                 :: "r"(dst), "l"(src), "r"(valid ? 16u : 0u));
}
#define CPCOMMIT asm volatile("cp.async.commit_group;")
#define CPWAIT(n) asm volatile("cp.async.wait_group %0;" :: "n"(n))

#define AST 20
#define BST 72

// one BK=16 chunk, 3xTF32 compensated
__device__ __forceinline__ void mma_compute(const float* Ab, const float* Bb,
                                            int wm, int wn, int lane,
                                            float acc[2][4][4]) {
#pragma unroll
    for (int ks = 0; ks < 16; ks += 8) {
        TF2 bf[4][2];
#pragma unroll
        for (int ni = 0; ni < 4; ni++) {
            int c = wn * 32 + ni * 8 + (lane >> 2);
            bf[ni][0] = tfsplit(Bb[(ks + (lane & 3)) * BST + c]);
            bf[ni][1] = tfsplit(Bb[(ks + (lane & 3) + 4) * BST + c]);
        }
#pragma unroll
        for (int mi = 0; mi < 2; mi++) {
            int r = wm * 32 + mi * 16 + (lane >> 2);
            const float* ap = Ab + r * AST + ks + (lane & 3);
            TF2 a0 = tfsplit(ap[0]);
            TF2 a2 = tfsplit(ap[4]);
            TF2 a1 = tfsplit(ap[8 * AST]);
            TF2 a3 = tfsplit(ap[8 * AST + 4]);
#pragma unroll
            for (int ni = 0; ni < 4; ni++) {
                mma8(acc[mi][ni], a0.h, a1.h, a2.h, a3.h, bf[ni][0].h, bf[ni][1].h);
                mma8(acc[mi][ni], a0.h, a1.h, a2.h, a3.h, bf[ni][0].l, bf[ni][1].l);
                mma8(acc[mi][ni], a0.l, a1.l, a2.l, a3.l, bf[ni][0].h, bf[ni][1].h);
            }
        }
    }
}

// ---------------- generic GEMM: C = A[MxK] @ W[KxN] + bias ----------------
__global__ void __launch_bounds__(256)
gemm_mma(const float* __restrict__ A, int lda,
         const float* __restrict__ Bm, int ldb,
         const float* __restrict__ bias,
         float* __restrict__ C, int ldc,
         int M, int N, int K, int patch_remap) {
    __shared__ float As[2][128 * AST];
    __shared__ float Bs[2][16 * BST];
    int tid = threadIdx.x, lane = tid & 31, wid = tid >> 5;
    int wm = wid & 3, wn = wid >> 2;
    int row0 = blockIdx.y * 128, col0 = blockIdx.x * 64;
    float acc[2][4][4] = {};
    uint32_t asb = (uint32_t)__cvta_generic_to_shared(&As[0][0]);
    uint32_t bsb = (uint32_t)__cvta_generic_to_shared(&Bs[0][0]);
    int KT = K >> 4;

    int am = tid >> 1, akq = (tid & 1) * 8;
    int bk = tid >> 4, bnq = (tid & 15) * 4;

    {
        bool va = (row0 + am) < M;
        const float* srcA = A + (va ? (size_t)(row0 + am) * lda : 0);
        cpa(asb + (am * AST + akq) * 4, srcA + akq, va);
        cpa(asb + (am * AST + akq + 4) * 4, srcA + akq + 4, va);
        cpa(bsb + (bk * BST + bnq) * 4, Bm + (size_t)bk * ldb + col0 + bnq, true);
        CPCOMMIT;
    }
    for (int kt = 0; kt < KT; kt++) {
        int buf = kt & 1;
        if (kt + 1 < KT) {
            int nb = buf ^ 1;
            bool va = (row0 + am) < M;
            const float* srcA = A + (va ? (size_t)(row0 + am) * lda : 0) + (kt + 1) * 16;
            cpa(asb + (nb * 128 * AST + am * AST + akq) * 4, srcA + akq, va);
            cpa(asb + (nb * 128 * AST + am * AST + akq + 4) * 4, srcA + akq + 4, va);
            cpa(bsb + (nb * 16 * BST + bk * BST + bnq) * 4,
                Bm + (size_t)((kt + 1) * 16 + bk) * ldb + col0 + bnq, true);
            CPCOMMIT;
            CPWAIT(1);
        } else {
            CPWAIT(0);
        }
        __syncthreads();
        mma_compute(&As[buf][0], &Bs[buf][0], wm, wn, lane, acc);
        __syncthreads();
    }

#pragma unroll
    for (int mi = 0; mi < 2; mi++)
#pragma unroll
        for (int ii = 0; ii < 2; ii++) {
            int r = row0 + wm * 32 + mi * 16 + (lane >> 2) + ii * 8;
            if (r >= M) continue;
            long orow = patch_remap ? ((long)r + (long)(r / NP) * 78 + 1) : (long)r;
#pragma unroll
            for (int ni = 0; ni < 4; ni++) {
                int c = col0 + wn * 32 + ni * 8 + (lane & 3) * 2;
                if (c + 1 < N) {
                    C[orow * ldc + c]     = acc[mi][ni][ii * 2 + 0] + bias[c];
                    C[orow * ldc + c + 1] = acc[mi][ni][ii * 2 + 1] + bias[c + 1];
                } else if (c < N) {
                    C[orow * ldc + c] = acc[mi][ni][ii * 2 + 0] + bias[c];
                }
            }
        }
}

// ---------------- scores = q @ k^T per (b,h), output stride SRS -------------
__global__ void __launch_bounds__(256) scores_mma() {
    const int z = blockIdx.z, b = z >> 1, hh = z & 1;
    const float* A  = g_q + (size_t)b * NTOK * EMB + hh * HD;
    const float* Bk = g_k + (size_t)b * NTOK * EMB + hh * HD;
    float* C = g_s + (size_t)z * NTOK * SRS;
    __shared__ float As[128 * AST];
    __shared__ float Bs[16 * BST];
    int tid = threadIdx.x, lane = tid & 31, wid = tid >> 5;
    int wm = wid & 3, wn = wid >> 2;
    int row0 = blockIdx.y * 128, col0 = blockIdx.x * 64;
    float acc[2][4][4] = {};
    uint32_t asb = (uint32_t)__cvta_generic_to_shared(As);
    int am = tid >> 1, akq = (tid & 1) * 8;
    int bc = tid >> 2, bkq = (tid & 3) * 4;

    for (int kt = 0; kt < HD / 16; kt++) {
        __syncthreads();
        bool va = (row0 + am) < NTOK;
        const float* srcA = A + (va ? (size_t)(row0 + am) * EMB : 0) + kt * 16;
        cpa(asb + (am * AST + akq) * 4, srcA + akq, va);
        cpa(asb + (am * AST + akq + 4) * 4, srcA + akq + 4, va);
        CPCOMMIT;
        int col = col0 + bc;
        float4 v = make_float4(0.f, 0.f, 0.f, 0.f);
        if (col < NTOK)
            v = *(const float4*)(Bk + (size_t)col * EMB + kt * 16 + bkq);
        Bs[(bkq + 0) * BST + bc] = v.x;
        Bs[(bkq + 1) * BST + bc] = v.y;
        Bs[(bkq + 2) * BST + bc] = v.z;
        Bs[(bkq + 3) * BST + bc] = v.w;
        CPWAIT(0);
        __syncthreads();
        mma_compute(As, Bs, wm, wn, lane, acc);
    }

#pragma unroll
    for (int mi = 0; mi < 2; mi++)
#pragma unroll
        for (int ii = 0; ii < 2; ii++) {
            int r = row0 + wm * 32 + mi * 16 + (lane >> 2) + ii * 8;
            if (r >= NTOK) continue;
#pragma unroll
            for (int ni = 0; ni < 4; ni++) {
                int c = col0 + wn * 32 + ni * 8 + (lane & 3) * 2;
                if (c < NTOK)     C[(size_t)r * SRS + c]     = acc[mi][ni][ii * 2 + 0];
                if (c + 1 < NTOK) C[(size_t)r * SRS + c + 1] = acc[mi][ni][ii * 2 + 1];
            }
        }
}

// ---------------- softmax row / sqrt(768), stride SRS, zero pads ------------
__global__ void softmax_kernel() {
    float* r = g_s + (size_t)blockIdx.x * SRS;
    int tid = threadIdx.x;
    __shared__ float sh[8];
    __shared__ float shb;

    float mx = -1e30f;
    for (int i = tid; i < NTOK; i += 256) mx = fmaxf(mx, r[i]);
    mx = warpMax(mx);
    if ((tid & 31) == 0) sh[tid >> 5] = mx;
    __syncthreads();
    if (tid == 0) {
        float m = sh[0];
#pragma unroll
        for (int i = 1; i < 8; i++) m = fmaxf(m, sh[i]);
        shb = m;
    }
    __syncthreads();
    mx = shb;

    float sum = 0.f;
    for (int i = tid; i < NTOK; i += 256) {
        float e = __expf(r[i] - mx);
        r[i] = e;
        sum += e;
    }
    sum = warpSum(sum);
    if ((tid & 31) == 0) sh[tid >> 5] = sum;
    __syncthreads();
    if (tid == 0) {
        float s = 0.f;
#pragma unroll
        for (int i = 0; i < 8; i++) s += sh[i];
        shb = s;
    }
    __syncthreads();
    float inv = INV_SQRT_E / shb;
    for (int i = tid; i < NTOK; i += 256) r[i] *= inv;
    if (tid < 2) r[NTOK + tid] = 0.f;
}

// ---------------- o = attn @ v per (b,h) ------------------------------------
__global__ void __launch_bounds__(256) av_mma() {
    const int z = blockIdx.z, b = z >> 1, hh = z & 1;
    const float* A  = g_s + (size_t)z * NTOK * SRS;
    const float* Bv = g_v + (size_t)b * NTOK * EMB + hh * HD;
    float* C = g_o + (size_t)b * NTOK * EMB + hh * HD;
    __shared__ float As[2][128 * AST];
    __shared__ float Bs[2][16 * BST];
    int tid = threadIdx.x, lane = tid & 31, wid = tid >> 5;
    int wm = wid & 3, wn = wid >> 2;
    int row0 = blockIdx.y * 128, col0 = blockIdx.x * 64;
    float acc[2][4][4] = {};
    uint32_t asb = (uint32_t)__cvta_generic_to_shared(&As[0][0]);
    uint32_t bsb = (uint32_t)__cvta_generic_to_shared(&Bs[0][0]);
    const int KT = SRS / 16;

    int am = tid >> 1, akq = (tid & 1) * 8;
    int bk = tid >> 4, bnq = (tid & 15) * 4;

    {
        bool va = (row0 + am) < NTOK;
        const float* srcA = A + (va ? (size_t)(row0 + am) * SRS : 0);
        cpa(asb + (am * AST + akq) * 4, srcA + akq, va);
        cpa(asb + (am * AST + akq + 4) * 4, srcA + akq + 4, va);
        bool vb = bk < NTOK;
        cpa(bsb + (bk * BST + bnq) * 4, Bv + (size_t)bk * EMB + col0 + bnq, vb);
        CPCOMMIT;
    }
    for (int kt = 0; kt < KT; kt++) {
        int buf = kt & 1;
        if (kt + 1 < KT) {
            int nb = buf ^ 1;
            bool va = (row0 + am) < NTOK;
            const float* srcA = A + (va ? (size_t)(row0 + am) * SRS : 0) + (kt + 1) * 16;
            cpa(asb + (nb * 128 * AST + am * AST + akq) * 4, srcA + akq, va);
            cpa(asb + (nb * 128 * AST + am * AST + akq + 4) * 4, srcA + akq + 4, va);
            int kk = (kt + 1) * 16 + bk;
            bool vb = kk < NTOK;
            const float* srcB = Bv + (size_t)(vb ? kk : 0) * EMB + col0 + bnq;
            cpa(bsb + (nb * 16 * BST + bk * BST + bnq) * 4, srcB, vb);
            CPCOMMIT;
            CPWAIT(1);
        } else {
            CPWAIT(0);
        }
        __syncthreads();
        mma_compute(&As[buf][0], &Bs[buf][0], wm, wn, lane, acc);
        __syncthreads();
    }

#pragma unroll
    for (int mi = 0; mi < 2; mi++)
#pragma unroll
        for (int ii = 0; ii < 2; ii++) {
            int r = row0 + wm * 32 + mi * 16 + (lane >> 2) + ii * 8;
            if (r >= NTOK) continue;
#pragma unroll
            for (int ni = 0; ni < 4; ni++) {
                int c = col0 + wn * 32 + ni * 8 + (lane & 3) * 2;
                C[(size_t)r * EMB + c]     = acc[mi][ni][ii * 2 + 0];
                C[(size_t)r * EMB + c + 1] = acc[mi][ni][ii * 2 + 1];
            }
        }
}

// ---------------- patch gather ----------------------------------------------
__global__ void patch_extract(const float* __restrict__ x, float* __restrict__ p) {
    long idx = (long)blockIdx.x * blockDim.x + threadIdx.x;
    const long total = (long)BATCH * 3 * 384 * 384;
    if (idx >= total) return;
    int ww = (int)(idx % 384);
    long t1 = idx / 384;
    int hh = (int)(t1 % 384);
    long t2 = t1 / 384;
    int c = (int)(t2 % 3);
    int b = (int)(t2 / 3);
    int j = (hh >> 4) * 24 + (ww >> 4);
    int k = (hh & 15) * 48 + (ww & 15) * 3 + c;
    p[((long)(b * NP + j)) * EMB + k] = x[idx];
}

__global__ void fill_cls_text(const float* __restrict__ cls, const float* __restrict__ txt) {
    long idx = (long)blockIdx.x * blockDim.x + threadIdx.x;
    const long total = (long)BATCH * (1 + NTXT) * EMB;
    if (idx >= total) return;
    int e = (int)(idx % EMB);
    long r = idx / EMB;
    int tok = (int)(r % (1 + NTXT));
    int b = (int)(r / (1 + NTXT));
    if (tok == 0)
        g_t[((long)b * NTOK) * EMB + e] = cls[e];
    else
        g_t[((long)b * NTOK + NP + tok) * EMB + e] = txt[((long)b * NTXT + (tok - 1)) * EMB + e];
}

// ---------------- LayerNorm 768 ----------------------------------------------
__global__ void ln768_kernel(const float* __restrict__ in,
                             const float* __restrict__ g,
                             const float* __restrict__ be,
                             float* __restrict__ out, int add) {
    long row = blockIdx.x;
    int tid = threadIdx.x;
    const float* r = in + row * EMB;
    float v0 = r[tid], v1 = r[tid + 256], v2 = r[tid + 512];
    float s = v0 + v1 + v2;
    float ss = v0 * v0 + v1 * v1 + v2 * v2;
    s = warpSum(s);
    ss = warpSum(ss);
    __shared__ float sh1[8], sh2[8];
    __shared__ float smean, srstd;
    if ((tid & 31) == 0) { sh1[tid >> 5] = s; sh2[tid >> 5] = ss; }
    __syncthreads();
    if (tid == 0) {
        float a = 0.f, b2 = 0.f;
#pragma unroll
        for (int i = 0; i < 8; i++) { a += sh1[i]; b2 += sh2[i]; }
        float mean = a * (1.f / 768.f);
        smean = mean;
        srstd = rsqrtf(b2 * (1.f / 768.f) - mean * mean + 1e-5f);
    }
    __syncthreads();
    float mean = smean, rstd = srstd;
    float* w = out + row * EMB;
    float vv[3] = {v0, v1, v2};
#pragma unroll
    for (int i = 0; i < 3; i++) {
        int c = tid + i * 256;
        float val = (vv[i] - mean) * rstd * g[c] + be[c];
        if (add) w[c] += val; else w[c] = val;
    }
}

__global__ void meanpool_kernel() {
    int b = blockIdx.x;
    int e = threadIdx.x;
    const float* base = g_t + (long)b * NTOK * EMB + e;
    float s = 0.f;
    for (int i = 0; i < NTOK; i++) s += base[(long)i * EMB];
    g_m[b * EMB + e] = s * (1.f / (float)NTOK);
}

// ---------------- launch ------------------------------------------------------
extern "C" void kernel_launch(void* const* d_in, const int* in_sizes, int n_in,
                              void* d_out, int out_size) {
    const float* x    = (const float*)d_in[0];
    const float* txt  = (const float*)d_in[1];
    const float* Wpa  = (const float*)d_in[2];
    const float* bpa  = (const float*)d_in[3];
    const float* cls  = (const float*)d_in[4];
    const float* g1   = (const float*)d_in[5];
    const float* be1  = (const float*)d_in[6];
    const float* Wq   = (const float*)d_in[7];
    const float* bq   = (const float*)d_in[8];
    const float* Wk   = (const float*)d_in[9];
    const float* bk   = (const float*)d_in[10];
    const float* Wv   = (const float*)d_in[11];
    const float* bv   = (const float*)d_in[12];
    const float* Wp   = (const float*)d_in[13];
    const float* bp   = (const float*)d_in[14];
    const float* g2   = (const float*)d_in[15];
    const float* be2  = (const float*)d_in[16];
    const float* g3   = (const float*)d_in[17];
    const float* be3  = (const float*)d_in[18];
    const float* Wf   = (const float*)d_in[19];
    const float* bf   = (const float*)d_in[20];
    float* out = (float*)d_out;

    float *t, *h, *q, *k, *v, *o, *m;
    cudaGetSymbolAddress((void**)&t, g_t);
    cudaGetSymbolAddress((void**)&h, g_h);
    cudaGetSymbolAddress((void**)&q, g_q);
    cudaGetSymbolAddress((void**)&k, g_k);
    cudaGetSymbolAddress((void**)&v, g_v);
    cudaGetSymbolAddress((void**)&o, g_o);
    cudaGetSymbolAddress((void**)&m, g_m);

    const int MQKV = BATCH * NTOK;
    const int MPATCH = BATCH * NP;

    patch_extract<<<55296, 256>>>(x, o);
    fill_cls_text<<<7488, 256>>>(cls, txt);

    gemm_mma<<<dim3(12, 144), 256>>>(o, EMB, Wpa, EMB, bpa, t, EMB,
                                     MPATCH, EMB, EMB, 1);

    ln768_kernel<<<MQKV, 256>>>(t, g1, be1, h, 0);

    dim3 gq(12, (MQKV + 127) / 128);
    gemm_mma<<<gq, 256>>>(h, EMB, Wq, EMB, bq, q, EMB, MQKV, EMB, EMB, 0);
    gemm_mma<<<gq, 256>>>(h, EMB, Wk, EMB, bk, k, EMB, MQKV, EMB, EMB, 0);
    gemm_mma<<<gq, 256>>>(h, EMB, Wv, EMB, bv, v, EMB, MQKV, EMB, EMB, 0);

    scores_mma<<<dim3(11, 6, 64), 256>>>();
    softmax_kernel<<<64 * NTOK, 256>>>();
    av_mma<<<dim3(6, 6, 64), 256>>>();

    gemm_mma<<<gq, 256>>>(o, EMB, Wp, EMB, bp, h, EMB, MQKV, EMB, EMB, 0);
    ln768_kernel<<<MQKV, 256>>>(h, g2, be2, t, 1);

    meanpool_kernel<<<BATCH, 768>>>();
    ln768_kernel<<<BATCH, 256>>>(m, g3, be3, m, 0);
    gemm_mma<<<dim3(12, 1), 256>>>(m, EMB, Wf, EMB, bf, out, EMB, BATCH, EMB, EMB, 0);
}

// round 4
// speedup vs baseline: 2.2850x; 1.2303x over previous
#include <cuda_runtime.h>
#include <cstdint>

#define BATCH 32
#define NP    576
#define NTXT  77
#define NTOK  654
#define EMB   768
#define HD    384
#define SRS   656          // scores row stride (41*16)
#define INV_SQRT_E 0.03608439182435161f

// ---------------- scratch ----------------
__device__ float g_t[(size_t)BATCH * NTOK * EMB];
__device__ float g_h[(size_t)BATCH * NTOK * EMB];
__device__ float g_q[(size_t)BATCH * NTOK * EMB];
__device__ float g_k[(size_t)BATCH * NTOK * EMB];
__device__ float g_v[(size_t)BATCH * NTOK * EMB];
__device__ float g_o[(size_t)BATCH * NTOK * EMB];
__device__ float g_s[(size_t)BATCH * 2 * NTOK * SRS];
__device__ float g_m[BATCH * EMB];

// ---------------- reductions ----------------
__device__ __forceinline__ float warpSum(float v) {
#pragma unroll
    for (int o = 16; o; o >>= 1) v += __shfl_xor_sync(0xffffffffu, v, o);
    return v;
}
__device__ __forceinline__ float warpMax(float v) {
#pragma unroll
    for (int o = 16; o; o >>= 1) v = fmaxf(v, __shfl_xor_sync(0xffffffffu, v, o));
    return v;
}

// ---------------- bf16 split helpers ----------------
// pack bf16(x0) (low half) | bf16(x1) (high half); lo residuals likewise.
// lo = x - float(bf16(x)) is exact in fp32.
__device__ __forceinline__ void bsplit2(float x0, float x1, uint32_t& h, uint32_t& l) {
    uint32_t u0 = __float_as_uint(x0), u1 = __float_as_uint(x1);
    uint32_t h0 = (u0 + 0x8000u) & 0xffff0000u;
    uint32_t h1 = (u1 + 0x8000u) & 0xffff0000u;
    float l0 = x0 - __uint_as_float(h0);
    float l1 = x1 - __uint_as_float(h1);
    h = (h0 >> 16) | h1;
    asm("cvt.rn.bf16x2.f32 %0, %1, %2;" : "=r"(l) : "f"(l1), "f"(l0));
}

__device__ __forceinline__ void mma16(float c[4], uint32_t a0, uint32_t a1,
                                      uint32_t a2, uint32_t a3,
                                      uint32_t b0, uint32_t b1) {
    asm volatile(
        "mma.sync.aligned.m16n8k16.row.col.f32.bf16.bf16.f32 "
        "{%0,%1,%2,%3},{%4,%5,%6,%7},{%8,%9},{%0,%1,%2,%3};"
        : "+f"(c[0]), "+f"(c[1]), "+f"(c[2]), "+f"(c[3])
        : "r"(a0), "r"(a1), "r"(a2), "r"(a3), "r"(b0), "r"(b1));
}

// smem tile strides in b32 units: 8 k-pairs + 1 pad
#define AKP 9
#define ASZ (128 * AKP)     // 1152 u32
#define BSZ (64 * AKP)      // 576 u32

// one 128x64x16 chunk, 3-term bf16 compensated
__device__ __forceinline__ void mma_chunk(const uint32_t* __restrict__ Ah,
                                          const uint32_t* __restrict__ Al,
                                          const uint32_t* __restrict__ Bh,
                                          const uint32_t* __restrict__ Bl,
                                          int wm, int wn, int lane,
                                          float acc[2][4][4]) {
    int g = lane >> 2, t = lane & 3;
    uint32_t bh[4][2], bl[4][2];
#pragma unroll
    for (int ni = 0; ni < 4; ni++) {
        int c = wn * 32 + ni * 8 + g;
        bh[ni][0] = Bh[c * AKP + t];
        bh[ni][1] = Bh[c * AKP + t + 4];
        bl[ni][0] = Bl[c * AKP + t];
        bl[ni][1] = Bl[c * AKP + t + 4];
    }
#pragma unroll
    for (int mi = 0; mi < 2; mi++) {
        int r = wm * 32 + mi * 16 + g;
        uint32_t ah0 = Ah[r * AKP + t],       ah1 = Ah[(r + 8) * AKP + t];
        uint32_t ah2 = Ah[r * AKP + t + 4],   ah3 = Ah[(r + 8) * AKP + t + 4];
        uint32_t al0 = Al[r * AKP + t],       al1 = Al[(r + 8) * AKP + t];
        uint32_t al2 = Al[r * AKP + t + 4],   al3 = Al[(r + 8) * AKP + t + 4];
#pragma unroll
        for (int ni = 0; ni < 4; ni++) {
            mma16(acc[mi][ni], ah0, ah1, ah2, ah3, bh[ni][0], bh[ni][1]);
            mma16(acc[mi][ni], ah0, ah1, ah2, ah3, bl[ni][0], bl[ni][1]);
            mma16(acc[mi][ni], al0, al1, al2, al3, bh[ni][0], bh[ni][1]);
        }
    }
}

// store A regs (8 floats = k[ak..ak+7] of row am) as split bf16
__device__ __forceinline__ void storeA(uint32_t* Ah, uint32_t* Al, int am, int ak,
                                       float4 v0, float4 v1) {
    uint32_t h, l;
    int base = am * AKP + (ak >> 1);
    bsplit2(v0.x, v0.y, h, l); Ah[base + 0] = h; Al[base + 0] = l;
    bsplit2(v0.z, v0.w, h, l); Ah[base + 1] = h; Al[base + 1] = l;
    bsplit2(v1.x, v1.y, h, l); Ah[base + 2] = h; Al[base + 2] = l;
    bsplit2(v1.z, v1.w, h, l); Ah[base + 3] = h; Al[base + 3] = l;
}

// ---------------- generic GEMM: C = A[MxK] @ W[KxN] + bias -------------------
__global__ void __launch_bounds__(256)
gemm_mma(const float* __restrict__ A, int lda,
         const float* __restrict__ Bm, int ldb,
         const float* __restrict__ bias,
         float* __restrict__ C, int ldc,
         int M, int N, int K, int patch_remap) {
    __shared__ uint32_t SAh[2][ASZ], SAl[2][ASZ], SBh[2][BSZ], SBl[2][BSZ];
    int tid = threadIdx.x, lane = tid & 31, wid = tid >> 5;
    int wm = wid & 3, wn = wid >> 2;
    int row0 = blockIdx.y * 128, col0 = blockIdx.x * 64;
    float acc[2][4][4] = {};
    int KT = K >> 4;

    int am = tid >> 1, ak = (tid & 1) * 8;
    int bc2 = (tid & 31) * 2, bk2 = (tid >> 5) * 2;
    bool va = (row0 + am) < M;
    const float* aBase = A + (va ? (size_t)(row0 + am) * lda : 0);
    const float* bBase = Bm + col0 + bc2;

    float4 ra0, ra1, na0, na1;
    float2 rb0, rb1, nb0, nb1;
    ra0 = *(const float4*)(aBase + ak);
    ra1 = *(const float4*)(aBase + ak + 4);
    rb0 = *(const float2*)(bBase + (size_t)bk2 * ldb);
    rb1 = *(const float2*)(bBase + (size_t)(bk2 + 1) * ldb);

    for (int kt = 0; kt < KT; kt++) {
        if (kt + 1 < KT) {
            na0 = *(const float4*)(aBase + (kt + 1) * 16 + ak);
            na1 = *(const float4*)(aBase + (kt + 1) * 16 + ak + 4);
            nb0 = *(const float2*)(bBase + (size_t)((kt + 1) * 16 + bk2) * ldb);
            nb1 = *(const float2*)(bBase + (size_t)((kt + 1) * 16 + bk2 + 1) * ldb);
        }
        int buf = kt & 1;
        storeA(SAh[buf], SAl[buf], am, ak, ra0, ra1);
        uint32_t h, l;
        bsplit2(rb0.x, rb1.x, h, l);
        SBh[buf][bc2 * AKP + (bk2 >> 1)] = h; SBl[buf][bc2 * AKP + (bk2 >> 1)] = l;
        bsplit2(rb0.y, rb1.y, h, l);
        SBh[buf][(bc2 + 1) * AKP + (bk2 >> 1)] = h; SBl[buf][(bc2 + 1) * AKP + (bk2 >> 1)] = l;
        __syncthreads();
        mma_chunk(SAh[buf], SAl[buf], SBh[buf], SBl[buf], wm, wn, lane, acc);
        ra0 = na0; ra1 = na1; rb0 = nb0; rb1 = nb1;
    }

#pragma unroll
    for (int mi = 0; mi < 2; mi++)
#pragma unroll
        for (int ii = 0; ii < 2; ii++) {
            int r = row0 + wm * 32 + mi * 16 + (lane >> 2) + ii * 8;
            if (r >= M) continue;
            long orow = patch_remap ? ((long)r + (long)(r / NP) * 78 + 1) : (long)r;
#pragma unroll
            for (int ni = 0; ni < 4; ni++) {
                int c = col0 + wn * 32 + ni * 8 + (lane & 3) * 2;
                C[orow * ldc + c]     = acc[mi][ni][ii * 2 + 0] + bias[c];
                C[orow * ldc + c + 1] = acc[mi][ni][ii * 2 + 1] + bias[c + 1];
            }
        }
}

// ---------------- scores = q @ k^T per (b,h) ---------------------------------
__global__ void __launch_bounds__(256) scores_mma() {
    const int z = blockIdx.z, b = z >> 1, hh = z & 1;
    const float* A  = g_q + (size_t)b * NTOK * EMB + hh * HD;
    const float* Bk = g_k + (size_t)b * NTOK * EMB + hh * HD;
    float* C = g_s + (size_t)z * NTOK * SRS;
    __shared__ uint32_t SAh[2][ASZ], SAl[2][ASZ], SBh[2][BSZ], SBl[2][BSZ];
    int tid = threadIdx.x, lane = tid & 31, wid = tid >> 5;
    int wm = wid & 3, wn = wid >> 2;
    int row0 = blockIdx.y * 128, col0 = blockIdx.x * 64;
    float acc[2][4][4] = {};
    const int KT = HD / 16;   // 24

    int am = tid >> 1, ak = (tid & 1) * 8;
    int bc = tid >> 2, bkq = (tid & 3) * 4;
    bool va = (row0 + am) < NTOK;
    bool vb = (col0 + bc) < NTOK;
    const float* aBase = A + (va ? (size_t)(row0 + am) * EMB : 0);
    const float* bBase = Bk + (vb ? (size_t)(col0 + bc) * EMB : 0);

    float4 ra0, ra1, rb, na0, na1, nb;
    ra0 = *(const float4*)(aBase + ak);
    ra1 = *(const float4*)(aBase + ak + 4);
    rb  = *(const float4*)(bBase + bkq);

    for (int kt = 0; kt < KT; kt++) {
        if (kt + 1 < KT) {
            na0 = *(const float4*)(aBase + (kt + 1) * 16 + ak);
            na1 = *(const float4*)(aBase + (kt + 1) * 16 + ak + 4);
            nb  = *(const float4*)(bBase + (kt + 1) * 16 + bkq);
        }
        int buf = kt & 1;
        storeA(SAh[buf], SAl[buf], am, ak, ra0, ra1);
        uint32_t h, l;
        int bb = bc * AKP + (bkq >> 1);
        bsplit2(rb.x, rb.y, h, l); SBh[buf][bb + 0] = h; SBl[buf][bb + 0] = l;
        bsplit2(rb.z, rb.w, h, l); SBh[buf][bb + 1] = h; SBl[buf][bb + 1] = l;
        __syncthreads();
        mma_chunk(SAh[buf], SAl[buf], SBh[buf], SBl[buf], wm, wn, lane, acc);
        ra0 = na0; ra1 = na1; rb = nb;
    }

#pragma unroll
    for (int mi = 0; mi < 2; mi++)
#pragma unroll
        for (int ii = 0; ii < 2; ii++) {
            int r = row0 + wm * 32 + mi * 16 + (lane >> 2) + ii * 8;
            if (r >= NTOK) continue;
#pragma unroll
            for (int ni = 0; ni < 4; ni++) {
                int c = col0 + wn * 32 + ni * 8 + (lane & 3) * 2;
                if (c < NTOK)     C[(size_t)r * SRS + c]     = acc[mi][ni][ii * 2 + 0];
                if (c + 1 < NTOK) C[(size_t)r * SRS + c + 1] = acc[mi][ni][ii * 2 + 1];
            }
        }
}

// ---------------- o = attn @ v per (b,h) -------------------------------------
__global__ void __launch_bounds__(256) av_mma() {
    const int z = blockIdx.z, b = z >> 1, hh = z & 1;
    const float* A  = g_s + (size_t)z * NTOK * SRS;            // [654, 656]
    const float* Bv = g_v + (size_t)b * NTOK * EMB + hh * HD;  // ldb=EMB
    float* C = g_o + (size_t)b * NTOK * EMB + hh * HD;
    __shared__ uint32_t SAh[2][ASZ], SAl[2][ASZ], SBh[2][BSZ], SBl[2][BSZ];
    int tid = threadIdx.x, lane = tid & 31, wid = tid >> 5;
    int wm = wid & 3, wn = wid >> 2;
    int row0 = blockIdx.y * 128, col0 = blockIdx.x * 64;
    float acc[2][4][4] = {};
    const int KT = SRS / 16;   // 41

    int am = tid >> 1, ak = (tid & 1) * 8;
    int bc2 = (tid & 31) * 2, bk2 = (tid >> 5) * 2;
    bool va = (row0 + am) < NTOK;
    const float* aBase = A + (va ? (size_t)(row0 + am) * SRS : 0);

    float4 ra0, ra1, na0, na1;
    float2 rb0, rb1, nb0, nb1;
    ra0 = *(const float4*)(aBase + ak);
    ra1 = *(const float4*)(aBase + ak + 4);
    {
        int k0 = bk2, k1 = bk2 + 1;
        rb0 = *(const float2*)(Bv + (size_t)(k0 < NTOK ? k0 : 0) * EMB + col0 + bc2);
        rb1 = *(const float2*)(Bv + (size_t)(k1 < NTOK ? k1 : 0) * EMB + col0 + bc2);
    }

    for (int kt = 0; kt < KT; kt++) {
        if (kt + 1 < KT) {
            na0 = *(const float4*)(aBase + (kt + 1) * 16 + ak);
            na1 = *(const float4*)(aBase + (kt + 1) * 16 + ak + 4);
            int k0 = (kt + 1) * 16 + bk2, k1 = k0 + 1;
            nb0 = *(const float2*)(Bv + (size_t)(k0 < NTOK ? k0 : 0) * EMB + col0 + bc2);
            nb1 = *(const float2*)(Bv + (size_t)(k1 < NTOK ? k1 : 0) * EMB + col0 + bc2);
        }
        int buf = kt & 1;
        storeA(SAh[buf], SAl[buf], am, ak, ra0, ra1);
        uint32_t h, l;
        bsplit2(rb0.x, rb1.x, h, l);
        SBh[buf][bc2 * AKP + (bk2 >> 1)] = h; SBl[buf][bc2 * AKP + (bk2 >> 1)] = l;
        bsplit2(rb0.y, rb1.y, h, l);
        SBh[buf][(bc2 + 1) * AKP + (bk2 >> 1)] = h; SBl[buf][(bc2 + 1) * AKP + (bk2 >> 1)] = l;
        __syncthreads();
        mma_chunk(SAh[buf], SAl[buf], SBh[buf], SBl[buf], wm, wn, lane, acc);
        ra0 = na0; ra1 = na1; rb0 = nb0; rb1 = nb1;
    }

#pragma unroll
    for (int mi = 0; mi < 2; mi++)
#pragma unroll
        for (int ii = 0; ii < 2; ii++) {
            int r = row0 + wm * 32 + mi * 16 + (lane >> 2) + ii * 8;
            if (r >= NTOK) continue;
#pragma unroll
            for (int ni = 0; ni < 4; ni++) {
                int c = col0 + wn * 32 + ni * 8 + (lane & 3) * 2;
                C[(size_t)r * EMB + c]     = acc[mi][ni][ii * 2 + 0];
                C[(size_t)r * EMB + c + 1] = acc[mi][ni][ii * 2 + 1];
            }
        }
}

// ---------------- softmax row / sqrt(768), zero pad cols ---------------------
__global__ void softmax_kernel() {
    float* r = g_s + (size_t)blockIdx.x * SRS;
    int tid = threadIdx.x;
    __shared__ float sh[8];
    __shared__ float shb;

    float mx = -1e30f;
    for (int i = tid; i < NTOK; i += 256) mx = fmaxf(mx, r[i]);
    mx = warpMax(mx);
    if ((tid & 31) == 0) sh[tid >> 5] = mx;
    __syncthreads();
    if (tid == 0) {
        float m = sh[0];
#pragma unroll
        for (int i = 1; i < 8; i++) m = fmaxf(m, sh[i]);
        shb = m;
    }
    __syncthreads();
    mx = shb;

    float sum = 0.f;
    for (int i = tid; i < NTOK; i += 256) {
        float e = __expf(r[i] - mx);
        r[i] = e;
        sum += e;
    }
    sum = warpSum(sum);
    if ((tid & 31) == 0) sh[tid >> 5] = sum;
    __syncthreads();
    if (tid == 0) {
        float s = 0.f;
#pragma unroll
        for (int i = 0; i < 8; i++) s += sh[i];
        shb = s;
    }
    __syncthreads();
    float inv = INV_SQRT_E / shb;
    for (int i = tid; i < NTOK; i += 256) r[i] *= inv;
    if (tid < 2) r[NTOK + tid] = 0.f;
}

// ---------------- patch gather ------------------------------------------------
__global__ void patch_extract(const float* __restrict__ x, float* __restrict__ p) {
    long idx = (long)blockIdx.x * blockDim.x + threadIdx.x;
    const long total = (long)BATCH * 3 * 384 * 384;
    if (idx >= total) return;
    int ww = (int)(idx % 384);
    long t1 = idx / 384;
    int hh = (int)(t1 % 384);
    long t2 = t1 / 384;
    int c = (int)(t2 % 3);
    int b = (int)(t2 / 3);
    int j = (hh >> 4) * 24 + (ww >> 4);
    int k = (hh & 15) * 48 + (ww & 15) * 3 + c;
    p[((long)(b * NP + j)) * EMB + k] = x[idx];
}

__global__ void fill_cls_text(const float* __restrict__ cls, const float* __restrict__ txt) {
    long idx = (long)blockIdx.x * blockDim.x + threadIdx.x;
    const long total = (long)BATCH * (1 + NTXT) * EMB;
    if (idx >= total) return;
    int e = (int)(idx % EMB);
    long r = idx / EMB;
    int tok = (int)(r % (1 + NTXT));
    int b = (int)(r / (1 + NTXT));
    if (tok == 0)
        g_t[((long)b * NTOK) * EMB + e] = cls[e];
    else
        g_t[((long)b * NTOK + NP + tok) * EMB + e] = txt[((long)b * NTXT + (tok - 1)) * EMB + e];
}

// ---------------- LayerNorm 768 ------------------------------------------------
__global__ void ln768_kernel(const float* __restrict__ in,
                             const float* __restrict__ g,
                             const float* __restrict__ be,
                             float* __restrict__ out, int add) {
    long row = blockIdx.x;
    int tid = threadIdx.x;
    const float* r = in + row * EMB;
    float v0 = r[tid], v1 = r[tid + 256], v2 = r[tid + 512];
    float s = v0 + v1 + v2;
    float ss = v0 * v0 + v1 * v1 + v2 * v2;
    s = warpSum(s);
    ss = warpSum(ss);
    __shared__ float sh1[8], sh2[8];
    __shared__ float smean, srstd;
    if ((tid & 31) == 0) { sh1[tid >> 5] = s; sh2[tid >> 5] = ss; }
    __syncthreads();
    if (tid == 0) {
        float a = 0.f, b2 = 0.f;
#pragma unroll
        for (int i = 0; i < 8; i++) { a += sh1[i]; b2 += sh2[i]; }
        float mean = a * (1.f / 768.f);
        smean = mean;
        srstd = rsqrtf(b2 * (1.f / 768.f) - mean * mean + 1e-5f);
    }
    __syncthreads();
    float mean = smean, rstd = srstd;
    float* w = out + row * EMB;
    float vv[3] = {v0, v1, v2};
#pragma unroll
    for (int i = 0; i < 3; i++) {
        int c = tid + i * 256;
        float val = (vv[i] - mean) * rstd * g[c] + be[c];
        if (add) w[c] += val; else w[c] = val;
    }
}

__global__ void meanpool_kernel() {
    int b = blockIdx.x;
    int e = threadIdx.x;
    const float* base = g_t + (long)b * NTOK * EMB + e;
    float s = 0.f;
    for (int i = 0; i < NTOK; i++) s += base[(long)i * EMB];
    g_m[b * EMB + e] = s * (1.f / (float)NTOK);
}

// ---------------- launch --------------------------------------------------------
extern "C" void kernel_launch(void* const* d_in, const int* in_sizes, int n_in,
                              void* d_out, int out_size) {
    const float* x    = (const float*)d_in[0];
    const float* txt  = (const float*)d_in[1];
    const float* Wpa  = (const float*)d_in[2];
    const float* bpa  = (const float*)d_in[3];
    const float* cls  = (const float*)d_in[4];
    const float* g1   = (const float*)d_in[5];
    const float* be1  = (const float*)d_in[6];
    const float* Wq   = (const float*)d_in[7];
    const float* bq   = (const float*)d_in[8];
    const float* Wk   = (const float*)d_in[9];
    const float* bk   = (const float*)d_in[10];
    const float* Wv   = (const float*)d_in[11];
    const float* bv   = (const float*)d_in[12];
    const float* Wp   = (const float*)d_in[13];
    const float* bp   = (const float*)d_in[14];
    const float* g2   = (const float*)d_in[15];
    const float* be2  = (const float*)d_in[16];
    const float* g3   = (const float*)d_in[17];
    const float* be3  = (const float*)d_in[18];
    const float* Wf   = (const float*)d_in[19];
    const float* bf   = (const float*)d_in[20];
    float* out = (float*)d_out;

    float *t, *h, *q, *k, *v, *o, *m;
    cudaGetSymbolAddress((void**)&t, g_t);
    cudaGetSymbolAddress((void**)&h, g_h);
    cudaGetSymbolAddress((void**)&q, g_q);
    cudaGetSymbolAddress((void**)&k, g_k);
    cudaGetSymbolAddress((void**)&v, g_v);
    cudaGetSymbolAddress((void**)&o, g_o);
    cudaGetSymbolAddress((void**)&m, g_m);

    const int MQKV = BATCH * NTOK;    // 20928
    const int MPATCH = BATCH * NP;    // 18432

    patch_extract<<<55296, 256>>>(x, o);
    fill_cls_text<<<7488, 256>>>(cls, txt);

    gemm_mma<<<dim3(12, 144), 256>>>(o, EMB, Wpa, EMB, bpa, t, EMB,
                                     MPATCH, EMB, EMB, 1);

    ln768_kernel<<<MQKV, 256>>>(t, g1, be1, h, 0);

    dim3 gq(12, (MQKV + 127) / 128);
    gemm_mma<<<gq, 256>>>(h, EMB, Wq, EMB, bq, q, EMB, MQKV, EMB, EMB, 0);
    gemm_mma<<<gq, 256>>>(h, EMB, Wk, EMB, bk, k, EMB, MQKV, EMB, EMB, 0);
    gemm_mma<<<gq, 256>>>(h, EMB, Wv, EMB, bv, v, EMB, MQKV, EMB, EMB, 0);

    scores_mma<<<dim3(11, 6, 64), 256>>>();
    softmax_kernel<<<64 * NTOK, 256>>>();
    av_mma<<<dim3(6, 6, 64), 256>>>();

    gemm_mma<<<gq, 256>>>(o, EMB, Wp, EMB, bp, h, EMB, MQKV, EMB, EMB, 0);
    ln768_kernel<<<MQKV, 256>>>(h, g2, be2, t, 1);

    meanpool_kernel<<<BATCH, 768>>>();
    ln768_kernel<<<BATCH, 256>>>(m, g3, be3, m, 0);
    gemm_mma<<<dim3(12, 1), 256>>>(m, EMB, Wf, EMB, bf, out, EMB, BATCH, EMB, EMB, 0);
}

// round 5
// speedup vs baseline: 2.5801x; 1.1292x over previous
#include <cuda_runtime.h>
#include <cstdint>

#define BATCH 32
#define NP    576
#define NTXT  77
#define NTOK  654
#define EMB   768
#define HD    384
#define SRS   656          // scores row stride & padded token count (41*16)
#define INV_SQRT_E 0.03608439182435161f
#define AKP   12           // smem row stride in u32 (48B: 16B-aligned, conflict-free)
#define ATW   (128*AKP)
#define BTW   (64*AKP)

// ---------------- fp32 scratch ----------------
__device__ float g_t[(size_t)BATCH * NTOK * EMB];     // token stream
__device__ float g_f[(size_t)BATCH * NTOK * EMB];     // patches fp32, later proj out
__device__ float g_v[(size_t)BATCH * NTOK * EMB];     // v fp32
__device__ float g_s[(size_t)BATCH * 2 * NTOK * SRS]; // scores fp32
__device__ float g_m[BATCH * EMB];

// ---------------- split bf16 buffers (u32 = packed pair along k) -------------
#define PAW ((size_t)18432 * 768 / 2)
#define HQW ((size_t)20928 * 768 / 2)
#define SXW ((size_t)64 * NTOK * SRS / 2)
#define VTW ((size_t)BATCH * EMB * SRS / 2)
__device__ uint32_t g_pa_h[PAW], g_pa_l[PAW];
__device__ uint32_t g_h_h[HQW],  g_h_l[HQW];
__device__ uint32_t g_q_h[HQW],  g_q_l[HQW];
__device__ uint32_t g_k_h[HQW],  g_k_l[HQW];
__device__ uint32_t g_o_h[HQW],  g_o_l[HQW];
__device__ uint32_t g_sx_h[SXW], g_sx_l[SXW];
__device__ uint32_t g_vt_h[VTW], g_vt_l[VTW];
__device__ uint32_t g_m_h[32*768/2], g_m_l[32*768/2];
__device__ uint16_t g_wh[6][768*768], g_wl[6][768*768];  // transposed [N][K]

// ---------------- helpers ----------------
__device__ __forceinline__ float warpSum(float v) {
#pragma unroll
    for (int o = 16; o; o >>= 1) v += __shfl_xor_sync(0xffffffffu, v, o);
    return v;
}
__device__ __forceinline__ float warpMax(float v) {
#pragma unroll
    for (int o = 16; o; o >>= 1) v = fmaxf(v, __shfl_xor_sync(0xffffffffu, v, o));
    return v;
}
// hi = bf16(x) (nearest-up), lo = bf16(x - hi); split is exact in fp32.
__device__ __forceinline__ void bsplit1(float x, uint16_t& h, uint16_t& l) {
    uint32_t u = __float_as_uint(x);
    uint32_t hu = (u + 0x8000u) & 0xffff0000u;
    float lo = x - __uint_as_float(hu);
    h = (uint16_t)(hu >> 16);
    l = (uint16_t)((__float_as_uint(lo) + 0x8000u) >> 16);
}
// packed pair: low half = x0, high half = x1
__device__ __forceinline__ void bsplit2(float x0, float x1, uint32_t& h, uint32_t& l) {
    uint16_t h0, l0, h1, l1;
    bsplit1(x0, h0, l0);
    bsplit1(x1, h1, l1);
    h = (uint32_t)h0 | ((uint32_t)h1 << 16);
    l = (uint32_t)l0 | ((uint32_t)l1 << 16);
}
__device__ __forceinline__ void mma16(float c[4], uint32_t a0, uint32_t a1,
                                      uint32_t a2, uint32_t a3,
                                      uint32_t b0, uint32_t b1) {
    asm volatile(
        "mma.sync.aligned.m16n8k16.row.col.f32.bf16.bf16.f32 "
        "{%0,%1,%2,%3},{%4,%5,%6,%7},{%8,%9},{%0,%1,%2,%3};"
        : "+f"(c[0]), "+f"(c[1]), "+f"(c[2]), "+f"(c[3])
        : "r"(a0), "r"(a1), "r"(a2), "r"(a3), "r"(b0), "r"(b1));
}
__device__ __forceinline__ void cpa(uint32_t dst, const void* src) {
    asm volatile("cp.async.cg.shared.global [%0], [%1], 16;"
                 :: "r"(dst), "l"(src));
}
#define CPCOMMIT asm volatile("cp.async.commit_group;")
#define CPWAIT(n) asm volatile("cp.async.wait_group %0;" :: "n"(n))

// one 128x64x16 chunk, 3-term bf16 compensated
__device__ __forceinline__ void mma_chunk(const uint32_t* __restrict__ Ah,
                                          const uint32_t* __restrict__ Al,
                                          const uint32_t* __restrict__ Bh,
                                          const uint32_t* __restrict__ Bl,
                                          int wm, int wn, int lane,
                                          float acc[2][4][4]) {
    int g = lane >> 2, t = lane & 3;
    uint32_t bh[4][2], bl[4][2];
#pragma unroll
    for (int ni = 0; ni < 4; ni++) {
        int c = wn * 32 + ni * 8 + g;
        bh[ni][0] = Bh[c * AKP + t];
        bh[ni][1] = Bh[c * AKP + t + 4];
        bl[ni][0] = Bl[c * AKP + t];
        bl[ni][1] = Bl[c * AKP + t + 4];
    }
#pragma unroll
    for (int mi = 0; mi < 2; mi++) {
        int r = wm * 32 + mi * 16 + g;
        uint32_t ah0 = Ah[r * AKP + t],     ah1 = Ah[(r + 8) * AKP + t];
        uint32_t ah2 = Ah[r * AKP + t + 4], ah3 = Ah[(r + 8) * AKP + t + 4];
        uint32_t al0 = Al[r * AKP + t],     al1 = Al[(r + 8) * AKP + t];
        uint32_t al2 = Al[r * AKP + t + 4], al3 = Al[(r + 8) * AKP + t + 4];
#pragma unroll
        for (int ni = 0; ni < 4; ni++) {
            mma16(acc[mi][ni], ah0, ah1, ah2, ah3, bh[ni][0], bh[ni][1]);
            mma16(acc[mi][ni], ah0, ah1, ah2, ah3, bl[ni][0], bl[ni][1]);
            mma16(acc[mi][ni], al0, al1, al2, al3, bh[ni][0], bh[ni][1]);
        }
    }
}

// ---------------- generic GEMM: C = A(split)[MxK] @ BT(split)[NxK] + bias ----
__global__ void __launch_bounds__(256)
gemm_bf16(const uint16_t* __restrict__ Ah, const uint16_t* __restrict__ Al, int lda,
          const uint16_t* __restrict__ Bh, const uint16_t* __restrict__ Bl,
          const float* __restrict__ bias,
          float* __restrict__ Cf, uint32_t* __restrict__ Ch, uint32_t* __restrict__ Cl,
          int ldc, int M, int K, int remap) {
    __shared__ uint32_t SA[2][2][ATW];
    __shared__ uint32_t SB[2][2][BTW];
    int tid = threadIdx.x, lane = tid & 31, wid = tid >> 5;
    int wm = wid & 3, wn = wid >> 2;
    int row0 = blockIdx.y * 128, col0 = blockIdx.x * 64;
    float acc[2][4][4] = {};
    int KT = K >> 4;

    int arow = row0 + (tid >> 1); if (arow >= M) arow = M - 1;
    int aj = tid & 1;
    const uint16_t* aH = Ah + (size_t)arow * lda + aj * 8;
    const uint16_t* aL = Al + (size_t)arow * lda + aj * 8;
    uint32_t sa_h = (uint32_t)__cvta_generic_to_shared(&SA[0][0][(tid >> 1) * AKP + aj * 4]);
    uint32_t sa_l = (uint32_t)__cvta_generic_to_shared(&SA[0][1][(tid >> 1) * AKP + aj * 4]);
    int barr = tid >> 7, brem = tid & 127;
    int bcol = col0 + (brem >> 1), bj = brem & 1;
    const uint16_t* bP = (barr ? Bl : Bh) + (size_t)bcol * K + bj * 8;
    uint32_t sb = (uint32_t)__cvta_generic_to_shared(&SB[0][barr][(brem >> 1) * AKP + bj * 4]);
    const uint32_t ABUF = 2 * ATW * 4, BBUF = 2 * BTW * 4;

    cpa(sa_h, aH); cpa(sa_l, aL); cpa(sb, bP);
    CPCOMMIT;
    for (int kt = 0; kt < KT; kt++) {
        int buf = kt & 1;
        if (kt + 1 < KT) {
            int nb = buf ^ 1;
            cpa(sa_h + nb * ABUF, aH + (size_t)(kt + 1) * 16);
            cpa(sa_l + nb * ABUF, aL + (size_t)(kt + 1) * 16);
            cpa(sb + nb * BBUF, bP + (size_t)(kt + 1) * 16);
            CPCOMMIT; CPWAIT(1);
        } else CPWAIT(0);
        __syncthreads();
        mma_chunk(SA[buf][0], SA[buf][1], SB[buf][0], SB[buf][1], wm, wn, lane, acc);
        __syncthreads();
    }

    int g = lane >> 2, t = lane & 3;
#pragma unroll
    for (int mi = 0; mi < 2; mi++)
#pragma unroll
        for (int ii = 0; ii < 2; ii++) {
            int r = row0 + wm * 32 + mi * 16 + g + ii * 8;
            if (r >= M) continue;
            size_t orow = remap ? ((size_t)r + (size_t)(r / NP) * 78 + 1) : (size_t)r;
#pragma unroll
            for (int ni = 0; ni < 4; ni++) {
                int c = col0 + wn * 32 + ni * 8 + t * 2;
                float v0 = acc[mi][ni][ii * 2 + 0];
                float v1 = acc[mi][ni][ii * 2 + 1];
                if (bias) { v0 += bias[c]; v1 += bias[c + 1]; }
                size_t idx = orow * ldc + c;
                if (Cf) { Cf[idx] = v0; Cf[idx + 1] = v1; }
                if (Ch) {
                    uint32_t h, l;
                    bsplit2(v0, v1, h, l);
                    Ch[idx >> 1] = h; Cl[idx >> 1] = l;
                }
            }
        }
}

// ---------------- scores = q @ k^T per (b,h) ---------------------------------
__global__ void __launch_bounds__(256) scores_bf16() {
    const int z = blockIdx.z, b = z >> 1, hh = z & 1;
    const uint16_t* qh = (const uint16_t*)g_q_h;
    const uint16_t* ql = (const uint16_t*)g_q_l;
    const uint16_t* kh = (const uint16_t*)g_k_h;
    const uint16_t* kl = (const uint16_t*)g_k_l;
    float* C = g_s + (size_t)z * NTOK * SRS;
    __shared__ uint32_t SA[2][2][ATW];
    __shared__ uint32_t SB[2][2][BTW];
    int tid = threadIdx.x, lane = tid & 31, wid = tid >> 5;
    int wm = wid & 3, wn = wid >> 2;
    int row0 = blockIdx.y * 128, col0 = blockIdx.x * 64;
    float acc[2][4][4] = {};
    const int KT = HD >> 4;

    int arow = row0 + (tid >> 1); if (arow >= NTOK) arow = NTOK - 1;
    int aj = tid & 1;
    size_t abase = ((size_t)(b * NTOK) + arow) * EMB + hh * HD + aj * 8;
    const uint16_t* aH = qh + abase;
    const uint16_t* aL = ql + abase;
    uint32_t sa_h = (uint32_t)__cvta_generic_to_shared(&SA[0][0][(tid >> 1) * AKP + aj * 4]);
    uint32_t sa_l = (uint32_t)__cvta_generic_to_shared(&SA[0][1][(tid >> 1) * AKP + aj * 4]);
    int barr = tid >> 7, brem = tid & 127;
    int bcol = col0 + (brem >> 1); if (bcol >= NTOK) bcol = NTOK - 1;
    int bj = brem & 1;
    size_t bbase = ((size_t)(b * NTOK) + bcol) * EMB + hh * HD + bj * 8;
    const uint16_t* bP = (barr ? kl : kh) + bbase;
    uint32_t sb = (uint32_t)__cvta_generic_to_shared(&SB[0][barr][(brem >> 1) * AKP + bj * 4]);
    const uint32_t ABUF = 2 * ATW * 4, BBUF = 2 * BTW * 4;

    cpa(sa_h, aH); cpa(sa_l, aL); cpa(sb, bP);
    CPCOMMIT;
    for (int kt = 0; kt < KT; kt++) {
        int buf = kt & 1;
        if (kt + 1 < KT) {
            int nb = buf ^ 1;
            cpa(sa_h + nb * ABUF, aH + (size_t)(kt + 1) * 16);
            cpa(sa_l + nb * ABUF, aL + (size_t)(kt + 1) * 16);
            cpa(sb + nb * BBUF, bP + (size_t)(kt + 1) * 16);
            CPCOMMIT; CPWAIT(1);
        } else CPWAIT(0);
        __syncthreads();
        mma_chunk(SA[buf][0], SA[buf][1], SB[buf][0], SB[buf][1], wm, wn, lane, acc);
        __syncthreads();
    }

    int g = lane >> 2, t = lane & 3;
#pragma unroll
    for (int mi = 0; mi < 2; mi++)
#pragma unroll
        for (int ii = 0; ii < 2; ii++) {
            int r = row0 + wm * 32 + mi * 16 + g + ii * 8;
            if (r >= NTOK) continue;
#pragma unroll
            for (int ni = 0; ni < 4; ni++) {
                int c = col0 + wn * 32 + ni * 8 + t * 2;
                if (c < NTOK)     C[(size_t)r * SRS + c]     = acc[mi][ni][ii * 2 + 0];
                if (c + 1 < NTOK) C[(size_t)r * SRS + c + 1] = acc[mi][ni][ii * 2 + 1];
            }
        }
}

// ---------------- o = attn @ v per (b,h) -------------------------------------
__global__ void __launch_bounds__(256) av_bf16() {
    const int z = blockIdx.z, b = z >> 1, hh = z & 1;
    const uint16_t* sh16 = (const uint16_t*)g_sx_h;
    const uint16_t* sl16 = (const uint16_t*)g_sx_l;
    const uint16_t* vth = (const uint16_t*)g_vt_h;
    const uint16_t* vtl = (const uint16_t*)g_vt_l;
    __shared__ uint32_t SA[2][2][ATW];
    __shared__ uint32_t SB[2][2][BTW];
    int tid = threadIdx.x, lane = tid & 31, wid = tid >> 5;
    int wm = wid & 3, wn = wid >> 2;
    int row0 = blockIdx.y * 128, col0 = blockIdx.x * 64;
    float acc[2][4][4] = {};
    const int KT = SRS >> 4;   // 41

    int arow = row0 + (tid >> 1); if (arow >= NTOK) arow = NTOK - 1;
    int aj = tid & 1;
    size_t abase = ((size_t)z * NTOK + arow) * SRS + aj * 8;
    const uint16_t* aH = sh16 + abase;
    const uint16_t* aL = sl16 + abase;
    uint32_t sa_h = (uint32_t)__cvta_generic_to_shared(&SA[0][0][(tid >> 1) * AKP + aj * 4]);
    uint32_t sa_l = (uint32_t)__cvta_generic_to_shared(&SA[0][1][(tid >> 1) * AKP + aj * 4]);
    int barr = tid >> 7, brem = tid & 127;
    int bcol = col0 + (brem >> 1), bj = brem & 1;
    size_t bbase = ((size_t)b * EMB + hh * HD + bcol) * SRS + bj * 8;
    const uint16_t* bP = (barr ? vtl : vth) + bbase;
    uint32_t sb = (uint32_t)__cvta_generic_to_shared(&SB[0][barr][(brem >> 1) * AKP + bj * 4]);
    const uint32_t ABUF = 2 * ATW * 4, BBUF = 2 * BTW * 4;

    cpa(sa_h, aH); cpa(sa_l, aL); cpa(sb, bP);
    CPCOMMIT;
    for (int kt = 0; kt < KT; kt++) {
        int buf = kt & 1;
        if (kt + 1 < KT) {
            int nb = buf ^ 1;
            cpa(sa_h + nb * ABUF, aH + (size_t)(kt + 1) * 16);
            cpa(sa_l + nb * ABUF, aL + (size_t)(kt + 1) * 16);
            cpa(sb + nb * BBUF, bP + (size_t)(kt + 1) * 16);
            CPCOMMIT; CPWAIT(1);
        } else CPWAIT(0);
        __syncthreads();
        mma_chunk(SA[buf][0], SA[buf][1], SB[buf][0], SB[buf][1], wm, wn, lane, acc);
        __syncthreads();
    }

    int g = lane >> 2, t = lane & 3;
#pragma unroll
    for (int mi = 0; mi < 2; mi++)
#pragma unroll
        for (int ii = 0; ii < 2; ii++) {
            int r = row0 + wm * 32 + mi * 16 + g + ii * 8;
            if (r >= NTOK) continue;
#pragma unroll
            for (int ni = 0; ni < 4; ni++) {
                int c = col0 + wn * 32 + ni * 8 + t * 2;
                size_t idx = ((size_t)(b * NTOK) + r) * EMB + hh * HD + c;
                uint32_t h, l;
                bsplit2(acc[mi][ni][ii * 2 + 0], acc[mi][ni][ii * 2 + 1], h, l);
                g_o_h[idx >> 1] = h; g_o_l[idx >> 1] = l;
            }
        }
}

// ---------------- softmax row / sqrt(768) -> split bf16 ----------------------
__global__ void softmax_kernel() {
    size_t row = blockIdx.x;
    const float* r = g_s + row * SRS;
    uint16_t* oh = (uint16_t*)g_sx_h + row * SRS;
    uint16_t* ol = (uint16_t*)g_sx_l + row * SRS;
    int tid = threadIdx.x;
    __shared__ float sh[8];
    __shared__ float shb;

    float mx = -1e30f;
    for (int i = tid; i < NTOK; i += 256) mx = fmaxf(mx, r[i]);
    mx = warpMax(mx);
    if ((tid & 31) == 0) sh[tid >> 5] = mx;
    __syncthreads();
    if (tid == 0) {
        float m = sh[0];
#pragma unroll
        for (int i = 1; i < 8; i++) m = fmaxf(m, sh[i]);
        shb = m;
    }
    __syncthreads();
    mx = shb;

    float sum = 0.f;
    float ev[3];
    int cnt = 0;
    for (int i = tid; i < NTOK; i += 256) { ev[cnt] = __expf(r[i] - mx); sum += ev[cnt]; cnt++; }
    sum = warpSum(sum);
    if ((tid & 31) == 0) sh[tid >> 5] = sum;
    __syncthreads();
    if (tid == 0) {
        float s = 0.f;
#pragma unroll
        for (int i = 0; i < 8; i++) s += sh[i];
        shb = s;
    }
    __syncthreads();
    float inv = INV_SQRT_E / shb;
    cnt = 0;
    for (int i = tid; i < NTOK; i += 256) {
        uint16_t h, l;
        bsplit1(ev[cnt++] * inv, h, l);
        oh[i] = h; ol[i] = l;
    }
    if (tid < SRS - NTOK) { oh[NTOK + tid] = 0; ol[NTOK + tid] = 0; }
}

// ---------------- weight transpose + split: W[K][N] -> wT hi/lo [N][K] -------
__global__ void wsplit_kernel(const float* __restrict__ W,
                              uint16_t* __restrict__ oh, uint16_t* __restrict__ ol) {
    __shared__ float tile[32][33];
    int tx = threadIdx.x, ty = threadIdx.y;
    int k0 = blockIdx.x * 32, n0 = blockIdx.y * 32;
#pragma unroll
    for (int i = 0; i < 32; i += 8)
        tile[ty + i][tx] = W[(size_t)(k0 + ty + i) * 768 + n0 + tx];
    __syncthreads();
#pragma unroll
    for (int i = 0; i < 32; i += 8) {
        uint16_t h, l;
        bsplit1(tile[tx][ty + i], h, l);
        size_t idx = (size_t)(n0 + ty + i) * 768 + k0 + tx;
        oh[idx] = h; ol[idx] = l;
    }
}

// ---------------- v transpose + split: v[b][tok][emb] -> vT hi/lo [b][emb][SRS]
__global__ void vtrans_kernel() {
    __shared__ float tile[32][33];
    int tx = threadIdx.x, ty = threadIdx.y;
    int b = blockIdx.z;
    int t0 = blockIdx.x * 32, e0 = blockIdx.y * 32;
    const float* v = g_v + (size_t)b * NTOK * EMB;
#pragma unroll
    for (int i = 0; i < 32; i += 8) {
        int tok = t0 + ty + i;
        tile[ty + i][tx] = (tok < NTOK) ? v[(size_t)tok * EMB + e0 + tx] : 0.f;
    }
    __syncthreads();
    uint16_t* oh = (uint16_t*)g_vt_h;
    uint16_t* ol = (uint16_t*)g_vt_l;
#pragma unroll
    for (int i = 0; i < 32; i += 8) {
        int tok = t0 + tx, e = e0 + ty + i;
        if (tok < SRS) {
            uint16_t h, l;
            bsplit1(tile[tx][ty + i], h, l);
            size_t idx = ((size_t)b * EMB + e) * SRS + tok;
            oh[idx] = h; ol[idx] = l;
        }
    }
}

// ---------------- elementwise fp32 -> split packed ----------------------------
__global__ void split_pa_kernel(const float* __restrict__ in, long nWords) {
    long w = (long)blockIdx.x * blockDim.x + threadIdx.x;
    if (w >= nWords) return;
    float2 v = *(const float2*)(in + w * 2);
    uint32_t h, l;
    bsplit2(v.x, v.y, h, l);
    g_pa_h[w] = h; g_pa_l[w] = l;
}

// ---------------- patch gather -> g_f fp32 ------------------------------------
__global__ void patch_extract(const float* __restrict__ x) {
    long idx = (long)blockIdx.x * blockDim.x + threadIdx.x;
    const long total = (long)BATCH * 3 * 384 * 384;
    if (idx >= total) return;
    int ww = (int)(idx % 384);
    long t1 = idx / 384;
    int hh = (int)(t1 % 384);
    long t2 = t1 / 384;
    int c = (int)(t2 % 3);
    int b = (int)(t2 / 3);
    int j = (hh >> 4) * 24 + (ww >> 4);
    int k = (hh & 15) * 48 + (ww & 15) * 3 + c;
    g_f[((size_t)(b * NP + j)) * EMB + k] = x[idx];
}

__global__ void fill_cls_text(const float* __restrict__ cls, const float* __restrict__ txt) {
    long idx = (long)blockIdx.x * blockDim.x + threadIdx.x;
    const long total = (long)BATCH * (1 + NTXT) * EMB;
    if (idx >= total) return;
    int e = (int)(idx % EMB);
    long r = idx / EMB;
    int tok = (int)(r % (1 + NTXT));
    int b = (int)(r / (1 + NTXT));
    if (tok == 0)
        g_t[((size_t)b * NTOK) * EMB + e] = cls[e];
    else
        g_t[((size_t)b * NTOK + NP + tok) * EMB + e] = txt[((size_t)b * NTXT + (tok - 1)) * EMB + e];
}

// ---------------- LayerNorm 768 variants ---------------------------------------
__device__ __forceinline__ void ln_stats(const float* r, int tid, float v[3],
                                         float& mean, float& rstd) {
    v[0] = r[tid]; v[1] = r[tid + 256]; v[2] = r[tid + 512];
    float s = v[0] + v[1] + v[2];
    float ss = v[0] * v[0] + v[1] * v[1] + v[2] * v[2];
    s = warpSum(s); ss = warpSum(ss);
    __shared__ float sh1[8], sh2[8];
    __shared__ float smean, srstd;
    if ((tid & 31) == 0) { sh1[tid >> 5] = s; sh2[tid >> 5] = ss; }
    __syncthreads();
    if (tid == 0) {
        float a = 0.f, b2 = 0.f;
#pragma unroll
        for (int i = 0; i < 8; i++) { a += sh1[i]; b2 += sh2[i]; }
        float m = a * (1.f / 768.f);
        smean = m;
        srstd = rsqrtf(b2 * (1.f / 768.f) - m * m + 1e-5f);
    }
    __syncthreads();
    mean = smean; rstd = srstd;
}

__global__ void ln768_split(const float* __restrict__ in,
                            const float* __restrict__ g, const float* __restrict__ be,
                            uint16_t* __restrict__ oh, uint16_t* __restrict__ ol) {
    size_t row = blockIdx.x;
    int tid = threadIdx.x;
    float v[3], mean, rstd;
    ln_stats(in + row * EMB, tid, v, mean, rstd);
#pragma unroll
    for (int i = 0; i < 3; i++) {
        int c = tid + i * 256;
        float val = (v[i] - mean) * rstd * g[c] + be[c];
        uint16_t h, l;
        bsplit1(val, h, l);
        oh[row * EMB + c] = h; ol[row * EMB + c] = l;
    }
}

__global__ void ln768_add(const float* __restrict__ in,
                          const float* __restrict__ g, const float* __restrict__ be,
                          float* __restrict__ out) {
    size_t row = blockIdx.x;
    int tid = threadIdx.x;
    float v[3], mean, rstd;
    ln_stats(in + row * EMB, tid, v, mean, rstd);
#pragma unroll
    for (int i = 0; i < 3; i++) {
        int c = tid + i * 256;
        out[row * EMB + c] += (v[i] - mean) * rstd * g[c] + be[c];
    }
}

__global__ void meanpool_kernel() {
    int b = blockIdx.x;
    int e = threadIdx.x;
    const float* base = g_t + (size_t)b * NTOK * EMB + e;
    float s = 0.f;
    for (int i = 0; i < NTOK; i++) s += base[(size_t)i * EMB];
    g_m[b * EMB + e] = s * (1.f / (float)NTOK);
}

// ---------------- launch ---------------------------------------------------------
extern "C" void kernel_launch(void* const* d_in, const int* in_sizes, int n_in,
                              void* d_out, int out_size) {
    const float* x    = (const float*)d_in[0];
    const float* txt  = (const float*)d_in[1];
    const float* Wpa  = (const float*)d_in[2];
    const float* bpa  = (const float*)d_in[3];
    const float* cls  = (const float*)d_in[4];
    const float* g1   = (const float*)d_in[5];
    const float* be1  = (const float*)d_in[6];
    const float* Wq   = (const float*)d_in[7];
    const float* bq   = (const float*)d_in[8];
    const float* Wk   = (const float*)d_in[9];
    const float* bk   = (const float*)d_in[10];
    const float* Wv   = (const float*)d_in[11];
    const float* bv   = (const float*)d_in[12];
    const float* Wp   = (const float*)d_in[13];
    const float* bp   = (const float*)d_in[14];
    const float* g2   = (const float*)d_in[15];
    const float* be2  = (const float*)d_in[16];
    const float* g3   = (const float*)d_in[17];
    const float* be3  = (const float*)d_in[18];
    const float* Wf   = (const float*)d_in[19];
    const float* bf   = (const float*)d_in[20];
    float* out = (float*)d_out;

    float *t, *f, *m;
    uint16_t *wh, *wl, *pah, *pal, *hh, *hl, *qh, *ql, *kh, *kl, *oh, *ol, *mh, *ml;
    uint32_t *qhw, *qlw, *khw, *klw, *vw_dummy;
    float* v32;
    cudaGetSymbolAddress((void**)&t, g_t);
    cudaGetSymbolAddress((void**)&f, g_f);
    cudaGetSymbolAddress((void**)&m, g_m);
    cudaGetSymbolAddress((void**)&v32, g_v);
    cudaGetSymbolAddress((void**)&wh, g_wh);
    cudaGetSymbolAddress((void**)&wl, g_wl);
    cudaGetSymbolAddress((void**)&pah, g_pa_h);
    cudaGetSymbolAddress((void**)&pal, g_pa_l);
    cudaGetSymbolAddress((void**)&hh, g_h_h);
    cudaGetSymbolAddress((void**)&hl, g_h_l);
    cudaGetSymbolAddress((void**)&qh, g_q_h);
    cudaGetSymbolAddress((void**)&ql, g_q_l);
    cudaGetSymbolAddress((void**)&kh, g_k_h);
    cudaGetSymbolAddress((void**)&kl, g_k_l);
    cudaGetSymbolAddress((void**)&oh, g_o_h);
    cudaGetSymbolAddress((void**)&ol, g_o_l);
    cudaGetSymbolAddress((void**)&mh, g_m_h);
    cudaGetSymbolAddress((void**)&ml, g_m_l);
    (void)qhw; (void)qlw; (void)khw; (void)klw; (void)vw_dummy;

    const int MQKV = BATCH * NTOK;    // 20928
    const int MPATCH = BATCH * NP;    // 18432
    const size_t WSZ = 768 * 768;
    dim3 tb(32, 8), wgrid(24, 24);

    // weight transpose+split (0=Wpa 1=Wq 2=Wk 3=Wv 4=Wp 5=Wf)
    wsplit_kernel<<<wgrid, tb>>>(Wpa, wh + 0 * WSZ, wl + 0 * WSZ);
    wsplit_kernel<<<wgrid, tb>>>(Wq,  wh + 1 * WSZ, wl + 1 * WSZ);
    wsplit_kernel<<<wgrid, tb>>>(Wk,  wh + 2 * WSZ, wl + 2 * WSZ);
    wsplit_kernel<<<wgrid, tb>>>(Wv,  wh + 3 * WSZ, wl + 3 * WSZ);
    wsplit_kernel<<<wgrid, tb>>>(Wp,  wh + 4 * WSZ, wl + 4 * WSZ);
    wsplit_kernel<<<wgrid, tb>>>(Wf,  wh + 5 * WSZ, wl + 5 * WSZ);

    // patches
    patch_extract<<<55296, 256>>>(x);
    split_pa_kernel<<<(int)((PAW + 255) / 256), 256>>>(f, (long)PAW);
    fill_cls_text<<<7488, 256>>>(cls, txt);

    // patch GEMM -> t fp32 (remapped)
    gemm_bf16<<<dim3(12, 144), 256>>>(pah, pal, EMB, wh + 0 * WSZ, wl + 0 * WSZ,
                                      bpa, t, nullptr, nullptr, EMB, MPATCH, EMB, 1);

    // LN1 -> h split
    ln768_split<<<MQKV, 256>>>(t, g1, be1, hh, hl);

    // QKV
    dim3 gq(12, (MQKV + 127) / 128);
    gemm_bf16<<<gq, 256>>>(hh, hl, EMB, wh + 1 * WSZ, wl + 1 * WSZ, bq,
                           nullptr, (uint32_t*)qh, (uint32_t*)ql, EMB, MQKV, EMB, 0);
    gemm_bf16<<<gq, 256>>>(hh, hl, EMB, wh + 2 * WSZ, wl + 2 * WSZ, bk,
                           nullptr, (uint32_t*)kh, (uint32_t*)kl, EMB, MQKV, EMB, 0);
    gemm_bf16<<<gq, 256>>>(hh, hl, EMB, wh + 3 * WSZ, wl + 3 * WSZ, bv,
                           v32, nullptr, nullptr, EMB, MQKV, EMB, 0);

    // v transpose+split
    vtrans_kernel<<<dim3(21, 24, BATCH), tb>>>();

    // attention
    scores_bf16<<<dim3(11, 6, 64), 256>>>();
    softmax_kernel<<<64 * NTOK, 256>>>();
    av_bf16<<<dim3(6, 6, 64), 256>>>();

    // proj -> g_f fp32, then t += LN2(g_f)
    gemm_bf16<<<gq, 256>>>(oh, ol, EMB, wh + 4 * WSZ, wl + 4 * WSZ, bp,
                           f, nullptr, nullptr, EMB, MQKV, EMB, 0);
    ln768_add<<<MQKV, 256>>>(f, g2, be2, t);

    // pool, LN3 -> m split, final GEMM -> out
    meanpool_kernel<<<BATCH, 768>>>();
    ln768_split<<<BATCH, 256>>>(m, g3, be3, mh, ml);
    gemm_bf16<<<dim3(12, 1), 256>>>(mh, ml, EMB, wh + 5 * WSZ, wl + 5 * WSZ, bf,
                                    out, nullptr, nullptr, EMB, 32, EMB, 0);
}